// round 15
// baseline (speedup 1.0000x reference)
#include <cuda_runtime.h>
#include <cuda_bf16.h>
#include <cstdint>

// ---------------- problem constants ----------------
constexpr int Bn = 4;
constexpr int C  = 64;      // CIN == COUT
constexpr int H  = 192;
constexpr int Wd = 192;
constexpr int HW = H * Wd;          // 36864
constexpr int QS = Bn * C * HW;     // elems per matrix (q, k, or v)

// scratch: [mat(q=0,k=1,v=2)][b][ch][pixel]  (113 MB static device array)
__device__ float g_qkv[3 * QS];

// ================= Kernel A: projection GEMM =================
constexpr int STRIP = 128;          // pixels per strip
constexpr int KPAD  = 136;          // bf16 row stride (272 B)
constexpr int XBUF  = STRIP * KPAD; // bf16 elems per X buffer
constexpr int A_OFF_W    = 0;
constexpr int A_OFF_BIAS = A_OFF_W + 192 * KPAD * 2;   // 52224
constexpr int A_OFF_X    = A_OFF_BIAS + 192 * 4;       // 52992
constexpr int A_SMEM     = A_OFF_X + 2 * XBUF * 2;     // 122624 (1 CTA/SM)

__device__ __forceinline__ void mma16816(float* c, const uint32_t* a,
                                         uint32_t b0, uint32_t b1) {
    asm volatile(
        "mma.sync.aligned.m16n8k16.row.col.f32.bf16.bf16.f32 "
        "{%0,%1,%2,%3}, {%4,%5,%6,%7}, {%8,%9}, {%0,%1,%2,%3};"
        : "+f"(c[0]), "+f"(c[1]), "+f"(c[2]), "+f"(c[3])
        : "r"(a[0]), "r"(a[1]), "r"(a[2]), "r"(a[3]), "r"(b0), "r"(b1));
}
__device__ __forceinline__ void ldsm_x4(uint32_t* r, uint32_t addr) {
    asm volatile("ldmatrix.sync.aligned.m8n8.x4.shared.b16 {%0,%1,%2,%3}, [%4];"
        : "=r"(r[0]), "=r"(r[1]), "=r"(r[2]), "=r"(r[3]) : "r"(addr));
}
__device__ __forceinline__ uint32_t smem_u32(const void* p) {
    uint32_t a;
    asm("{ .reg .u64 t; cvta.to.shared.u64 t, %1; cvt.u32.u64 %0, t; }" : "=r"(a) : "l"(p));
    return a;
}
__device__ __forceinline__ uint32_t pack_bf16x2(float lo_f, float hi_f) {
    __nv_bfloat162 h = __floats2bfloat162_rn(lo_f, hi_f);
    return *reinterpret_cast<uint32_t*>(&h);
}
__device__ __forceinline__ float fast_ex2(float x) {
    float r;
    asm("ex2.approx.f32 %0, %1;" : "=f"(r) : "f"(x));
    return r;
}
constexpr float LOG2E = 1.4426950408889634f;

__global__ __launch_bounds__(512, 1)
void proj_kernel(const float* __restrict__ x,
                 const float* __restrict__ Wq, const float* __restrict__ bq,
                 const float* __restrict__ Wk, const float* __restrict__ bk,
                 const float* __restrict__ Wv, const float* __restrict__ bv)
{
    extern __shared__ char smem[];
    __nv_bfloat16* Ws = reinterpret_cast<__nv_bfloat16*>(smem + A_OFF_W);  // [192][KPAD]
    float* bsh        = reinterpret_cast<float*>(smem + A_OFF_BIAS);       // [192]
    __nv_bfloat16* Xs = reinterpret_cast<__nv_bfloat16*>(smem + A_OFF_X);  // [2][STRIP][KPAD]

    const int tid  = threadIdx.x;
    const int wid  = tid >> 5;
    const int lane = tid & 31;
    const uint32_t px0 = blockIdx.x * STRIP;

    // ---- build W split [hi | lo] (rows: q0-63 | k64-127 | v128-191) ----
    for (int i = tid; i < 192 * 32; i += 512) {
        int m  = i >> 5;
        int cp = i & 31;
        int c  = cp * 2;
        int mat = m >> 6;
        int ch  = m & 63;
        const float* Wsrc = (mat == 0) ? Wq : (mat == 1) ? Wk : Wv;
        float2 w = *reinterpret_cast<const float2*>(Wsrc + ch * C + c);
        __nv_bfloat16 h0b = __float2bfloat16(w.x);
        __nv_bfloat16 h1b = __float2bfloat16(w.y);
        float l0 = w.x - __bfloat162float(h0b);
        float l1 = w.y - __bfloat162float(h1b);
        uint32_t hi2 = ((uint32_t)*reinterpret_cast<uint16_t*>(&h0b)) |
                       ((uint32_t)*reinterpret_cast<uint16_t*>(&h1b) << 16);
        uint32_t lo2 = pack_bf16x2(l0, l1);
        uint32_t* row = reinterpret_cast<uint32_t*>(Ws + m * KPAD);
        row[cp]      = hi2;
        row[32 + cp] = lo2;
    }
    if (tid < 192) {
        int mat = tid >> 6;
        int ch  = tid & 63;
        bsh[tid] = ((mat == 0) ? bq : (mat == 1) ? bk : bv)[ch];
    }

    // warp tiling: 16 warps = 4 m-groups (48 rows) x 4 n-groups (32 px)
    const int mg  = wid >> 2;
    const int ngA = wid & 3;
    const int lrow = (lane & 7) + ((lane >> 3) & 1) * 8;
    const int lkof = (lane >> 4) * 8;
    const uint32_t xs_base = smem_u32(Xs);
    const uint32_t ws_base = smem_u32(Ws);

    // register-staged X load (8 iters x 2 channels)
    float xr0[8], xr1[8];

    auto loadX = [&](int b) {
        #pragma unroll
        for (int it = 0; it < 8; ++it) {
            int i  = tid + it * 512;
            int cp = i >> 7;                   // STRIP = 128
            int px = i & 127;
            const float* xp = x + (uint32_t)(b * C + cp * 2) * HW + px0 + px;
            xr0[it] = xp[0];
            xr1[it] = xp[HW];
        }
    };
    auto flushX = [&](int bs) {
        __nv_bfloat16* Xd = Xs + bs * XBUF;
        #pragma unroll
        for (int it = 0; it < 8; ++it) {
            int i  = tid + it * 512;
            int cp = i >> 7;
            int px = i & 127;
            float f0 = xr0[it], f1 = xr1[it];
            __nv_bfloat16 h0b = __float2bfloat16(f0);
            __nv_bfloat16 h1b = __float2bfloat16(f1);
            float l0 = f0 - __bfloat162float(h0b);
            float l1 = f1 - __bfloat162float(h1b);
            uint32_t hi2 = ((uint32_t)*reinterpret_cast<uint16_t*>(&h0b)) |
                           ((uint32_t)*reinterpret_cast<uint16_t*>(&h1b) << 16);
            uint32_t lo2 = pack_bf16x2(l0, l1);
            uint32_t* row = reinterpret_cast<uint32_t*>(Xd + px * KPAD);
            row[cp]      = hi2;
            row[32 + cp] = lo2;
        }
    };

    loadX(0);
    flushX(0);
    __syncthreads();      // W + X0 visible

    for (int b = 0; b < Bn; ++b) {
        if (b < 3) loadX(b + 1);     // LDGs drain under the GEMM below

        // ---- GEMM, term-grouped: per t load Ahi/Alo/Bhi/Blo once, 3 terms ----
        const uint32_t xb_base = xs_base + (uint32_t)((b & 1) * XBUF * 2);
        float acc[3][4][4];
        #pragma unroll
        for (int mt = 0; mt < 3; ++mt) {
            float b0v = bsh[mg * 48 + mt * 16 + (lane >> 2)];
            float b1v = bsh[mg * 48 + mt * 16 + (lane >> 2) + 8];
            #pragma unroll
            for (int jn = 0; jn < 4; ++jn) {
                acc[mt][jn][0] = b0v; acc[mt][jn][1] = b0v;
                acc[mt][jn][2] = b1v; acc[mt][jn][3] = b1v;
            }
        }
        #pragma unroll
        for (int t = 0; t < 4; ++t) {
            const int khi = t * 16;            // hi cols 0..63
            const int klo = 64 + t * 16;       // lo cols 64..127
            uint32_t ahi[3][4], alo[3][4];
            #pragma unroll
            for (int mt = 0; mt < 3; ++mt) {
                const uint32_t arow = ws_base +
                    (uint32_t)((mg * 48 + mt * 16 + lrow) * (KPAD * 2));
                ldsm_x4(ahi[mt], arow + (uint32_t)((khi + lkof) * 2));
                ldsm_x4(alo[mt], arow + (uint32_t)((klo + lkof) * 2));
            }
            #pragma unroll
            for (int nt = 0; nt < 2; ++nt) {
                const uint32_t brow = xb_base +
                    (uint32_t)((ngA * 32 + nt * 16 + lrow) * (KPAD * 2));
                uint32_t bhi[4], blo[4];
                ldsm_x4(bhi, brow + (uint32_t)((khi + lkof) * 2));
                ldsm_x4(blo, brow + (uint32_t)((klo + lkof) * 2));
                #pragma unroll
                for (int mt = 0; mt < 3; ++mt) {
                    mma16816(acc[mt][nt * 2 + 0], ahi[mt], bhi[0], bhi[2]);  // Whi*Xhi
                    mma16816(acc[mt][nt * 2 + 1], ahi[mt], bhi[1], bhi[3]);
                    mma16816(acc[mt][nt * 2 + 0], alo[mt], bhi[0], bhi[2]);  // Wlo*Xhi
                    mma16816(acc[mt][nt * 2 + 1], alo[mt], bhi[1], bhi[3]);
                    mma16816(acc[mt][nt * 2 + 0], ahi[mt], blo[0], blo[2]);  // Whi*Xlo
                    mma16816(acc[mt][nt * 2 + 1], ahi[mt], blo[1], blo[3]);
                }
            }
        }

        if (b < 3) flushX((b + 1) & 1);   // LDGs have landed by now

        // ---- store to scratch: [mat][b][ch][px] ----
        #pragma unroll
        for (int mt = 0; mt < 3; ++mt) {
            const int r0 = mg * 48 + mt * 16 + (lane >> 2);
            const int r1 = r0 + 8;
            float* d0 = g_qkv + (uint32_t)(((r0 >> 6) * Bn + b) * C + (r0 & 63)) * HW + px0;
            float* d1 = g_qkv + (uint32_t)(((r1 >> 6) * Bn + b) * C + (r1 & 63)) * HW + px0;
            #pragma unroll
            for (int jn = 0; jn < 4; ++jn) {
                const int col = ngA * 32 + jn * 8 + (lane & 3) * 2;
                *reinterpret_cast<float2*>(d0 + col) = make_float2(acc[mt][jn][0], acc[mt][jn][1]);
                *reinterpret_cast<float2*>(d1 + col) = make_float2(acc[mt][jn][2], acc[mt][jn][3]);
            }
        }
        __syncthreads();
    }
}

// ================= Kernel B: 9-tap per-channel softmax =================
// Thread = 1 channel x (4 wide x 2 tall) pixel block; halo rows loaded once
// and fed to both output rows (row-rolling reuse).
constexpr int TB    = 16;           // spatial tile
constexpr int HB    = TB + 2;       // 18 (halo)
constexpr int HPTS  = HB * HB;      // 324
constexpr int RS    = 24;           // halo row stride (floats): conflict-free LDS.128
constexpr int CAREA = HB * RS;      // 432 floats per channel
constexpr int B_SMEM = 2 * 16 * CAREA * 4;   // ks + vs = 55296 B (4 CTAs/SM)

__global__ __launch_bounds__(256, 4)
void attn_sm_kernel(float* __restrict__ out)
{
    extern __shared__ char smem[];
    float* ks = reinterpret_cast<float*>(smem);            // [16][CAREA]
    float* vs = ks + 16 * CAREA;                           // [16][CAREA]

    const int b   = blockIdx.z;
    const int ty0 = blockIdx.y * TB;
    const int tx0 = blockIdx.x * TB;
    const int tid = threadIdx.x;

    // assignment: warp = one channel-pair group; lane -> 4x2 pixel block
    const int chg = tid >> 5;           // 0..7
    const int t   = tid & 31;
    const int bri = t >> 2;             // 0..7 -> py0 = 2*bri
    const int bci = t & 3;              // 0..3 -> qx  = 4*bci
    const int py0 = bri * 2;
    const int qx  = bci * 4;

    const uint32_t kmat = (uint32_t)(1 * Bn + b) * C * HW;
    const uint32_t vmat = (uint32_t)(2 * Bn + b) * C * HW;
    const uint32_t qmat = (uint32_t)b * C * HW;
    const uint32_t qpix0 = (uint32_t)(ty0 + py0) * Wd + tx0 + qx;

    const bool interior = (ty0 != 0) && (ty0 != H - TB) && (tx0 != 0) && (tx0 != Wd - TB);
    const uint32_t ibase = (uint32_t)(ty0 - 1) * Wd + (uint32_t)(tx0 - 1);

    #pragma unroll 1
    for (int c0 = 0; c0 < C; c0 += 16) {
        if (c0 > 0) __syncthreads();    // prev compute done before smem overwrite

        // ---- load k,v chunk into [ch][hy*RS + hx] layout ----
        if (interior) {
            for (int i = tid; i < 16 * HPTS; i += 256) {
                int ch = i / HPTS;
                int e  = i - ch * HPTS;
                int hy = e / HB;
                int hx = e - hy * HB;
                uint32_t src = (uint32_t)(c0 + ch) * HW + ibase + (uint32_t)hy * Wd + hx;
                uint32_t dst = ch * CAREA + hy * RS + hx;
                ks[dst] = g_qkv[kmat + src];
                vs[dst] = g_qkv[vmat + src];
            }
        } else {
            for (int i = tid; i < 16 * HPTS; i += 256) {
                int ch = i / HPTS;
                int e  = i - ch * HPTS;
                int hy = e / HB;
                int hx = e - hy * HB;
                int gy = ty0 + hy - 1;
                gy = (gy < 0) ? -gy : ((gy >= H) ? (2 * H - 2 - gy) : gy);
                int gx = tx0 + hx - 1;
                gx = (gx < 0) ? -gx : ((gx >= Wd) ? (2 * Wd - 2 - gx) : gx);
                uint32_t src = (uint32_t)(c0 + ch) * HW + (uint32_t)gy * Wd + gx;
                uint32_t dst = ch * CAREA + hy * RS + hx;
                ks[dst] = g_qkv[kmat + src];
                vs[dst] = g_qkv[vmat + src];
            }
        }
        __syncthreads();

        // ---- softmax: 2 channel iters, rolling over 4 halo rows ----
        #pragma unroll 1
        for (int r = 0; r < 2; ++r) {
            const int ch = chg * 2 + r;             // 0..15
            const uint32_t plane = qmat + (uint32_t)(c0 + ch) * HW;
            float4 q0v = *reinterpret_cast<const float4*>(g_qkv + plane + qpix0);
            float4 q1v = *reinterpret_cast<const float4*>(g_qkv + plane + qpix0 + Wd);
            const float qq0[4] = {q0v.x * LOG2E, q0v.y * LOG2E, q0v.z * LOG2E, q0v.w * LOG2E};
            const float qq1[4] = {q1v.x * LOG2E, q1v.y * LOG2E, q1v.z * LOG2E, q1v.w * LOG2E};
            const float* kr = ks + ch * CAREA + py0 * RS + qx;
            const float* vr = vs + ch * CAREA + py0 * RS + qx;

            float s0[4] = {0.f, 0.f, 0.f, 0.f}, a0[4] = {0.f, 0.f, 0.f, 0.f};
            float s1[4] = {0.f, 0.f, 0.f, 0.f}, a1[4] = {0.f, 0.f, 0.f, 0.f};

            #pragma unroll
            for (int row = 0; row < 4; ++row) {
                float4 k0 = *reinterpret_cast<const float4*>(kr + row * RS);
                float4 k1 = *reinterpret_cast<const float4*>(kr + row * RS + 4);
                float4 v0 = *reinterpret_cast<const float4*>(vr + row * RS);
                float4 v1 = *reinterpret_cast<const float4*>(vr + row * RS + 4);
                const float kk[8] = {k0.x, k0.y, k0.z, k0.w, k1.x, k1.y, k1.z, k1.w};
                const float vv[8] = {v0.x, v0.y, v0.z, v0.w, v1.x, v1.y, v1.z, v1.w};
                if (row <= 2) {             // feeds output row 0
                    #pragma unroll
                    for (int p = 0; p < 4; ++p) {
                        #pragma unroll
                        for (int j = 0; j < 3; ++j) {
                            float e = fast_ex2(qq0[p] * kk[p + j]);
                            s0[p] += e;
                            a0[p] = fmaf(e, vv[p + j], a0[p]);
                        }
                    }
                }
                if (row >= 1) {             // feeds output row 1
                    #pragma unroll
                    for (int p = 0; p < 4; ++p) {
                        #pragma unroll
                        for (int j = 0; j < 3; ++j) {
                            float e = fast_ex2(qq1[p] * kk[p + j]);
                            s1[p] += e;
                            a1[p] = fmaf(e, vv[p + j], a1[p]);
                        }
                    }
                }
            }
            *reinterpret_cast<float4*>(out + plane + qpix0) =
                make_float4(__fdividef(a0[0], s0[0]), __fdividef(a0[1], s0[1]),
                            __fdividef(a0[2], s0[2]), __fdividef(a0[3], s0[3]));
            *reinterpret_cast<float4*>(out + plane + qpix0 + Wd) =
                make_float4(__fdividef(a1[0], s1[0]), __fdividef(a1[1], s1[1]),
                            __fdividef(a1[2], s1[2]), __fdividef(a1[3], s1[3]));
        }
    }
}

extern "C" void kernel_launch(void* const* d_in, const int* in_sizes, int n_in,
                              void* d_out, int out_size)
{
    const float* x  = (const float*)d_in[0];
    const float* Wq = (const float*)d_in[1];
    const float* bq = (const float*)d_in[2];
    const float* Wk = (const float*)d_in[3];
    const float* bk = (const float*)d_in[4];
    const float* Wv = (const float*)d_in[5];
    const float* bv = (const float*)d_in[6];
    float* out = (float*)d_out;

    cudaFuncSetAttribute(proj_kernel, cudaFuncAttributeMaxDynamicSharedMemorySize, A_SMEM);
    cudaFuncSetAttribute(attn_sm_kernel, cudaFuncAttributeMaxDynamicSharedMemorySize, B_SMEM);

    proj_kernel<<<HW / STRIP, 512, A_SMEM>>>(x, Wq, bq, Wk, bk, Wv, bv);   // 288 CTAs
    dim3 gridB(Wd / TB, H / TB, Bn);                                       // (12,12,4)
    attn_sm_kernel<<<gridB, 256, B_SMEM>>>(out);
}

// round 17
// speedup vs baseline: 1.1135x; 1.1135x over previous
#include <cuda_runtime.h>
#include <cuda_bf16.h>
#include <cstdint>

// ---------------- problem constants ----------------
constexpr int Bn = 4;
constexpr int C  = 64;      // CIN == COUT
constexpr int H  = 192;
constexpr int Wd = 192;
constexpr int HW = H * Wd;          // 36864
constexpr int QS = Bn * C * HW;     // elems per matrix (q, k, or v)

// scratch: [mat(q=0,k=1,v=2)][b][ch][pixel]  (113 MB static device array)
__device__ float g_qkv[3 * QS];

// ================= Kernel A: projection GEMM =================
constexpr int STRIP = 128;          // pixels per strip
constexpr int KPAD  = 136;          // bf16 row stride (272 B)
constexpr int XBUF  = STRIP * KPAD; // bf16 elems per X buffer
constexpr int A_OFF_W    = 0;
constexpr int A_OFF_BIAS = A_OFF_W + 192 * KPAD * 2;   // 52224
constexpr int A_OFF_X    = A_OFF_BIAS + 192 * 4;       // 52992
constexpr int A_SMEM     = A_OFF_X + 2 * XBUF * 2;     // 122624 (1 CTA/SM)

__device__ __forceinline__ void mma16816(float* c, const uint32_t* a,
                                         uint32_t b0, uint32_t b1) {
    asm volatile(
        "mma.sync.aligned.m16n8k16.row.col.f32.bf16.bf16.f32 "
        "{%0,%1,%2,%3}, {%4,%5,%6,%7}, {%8,%9}, {%0,%1,%2,%3};"
        : "+f"(c[0]), "+f"(c[1]), "+f"(c[2]), "+f"(c[3])
        : "r"(a[0]), "r"(a[1]), "r"(a[2]), "r"(a[3]), "r"(b0), "r"(b1));
}
__device__ __forceinline__ void ldsm_x4(uint32_t* r, uint32_t addr) {
    asm volatile("ldmatrix.sync.aligned.m8n8.x4.shared.b16 {%0,%1,%2,%3}, [%4];"
        : "=r"(r[0]), "=r"(r[1]), "=r"(r[2]), "=r"(r[3]) : "r"(addr));
}
__device__ __forceinline__ uint32_t smem_u32(const void* p) {
    uint32_t a;
    asm("{ .reg .u64 t; cvta.to.shared.u64 t, %1; cvt.u32.u64 %0, t; }" : "=r"(a) : "l"(p));
    return a;
}
__device__ __forceinline__ uint32_t pack_bf16x2(float lo_f, float hi_f) {
    __nv_bfloat162 h = __floats2bfloat162_rn(lo_f, hi_f);
    return *reinterpret_cast<uint32_t*>(&h);
}
__device__ __forceinline__ float fast_ex2(float x) {
    float r;
    asm("ex2.approx.f32 %0, %1;" : "=f"(r) : "f"(x));
    return r;
}
constexpr float LOG2E = 1.4426950408889634f;

__global__ __launch_bounds__(512, 1)
void proj_kernel(const float* __restrict__ x,
                 const float* __restrict__ Wq, const float* __restrict__ bq,
                 const float* __restrict__ Wk, const float* __restrict__ bk,
                 const float* __restrict__ Wv, const float* __restrict__ bv)
{
    extern __shared__ char smem[];
    __nv_bfloat16* Ws = reinterpret_cast<__nv_bfloat16*>(smem + A_OFF_W);  // [192][KPAD]
    float* bsh        = reinterpret_cast<float*>(smem + A_OFF_BIAS);       // [192]
    __nv_bfloat16* Xs = reinterpret_cast<__nv_bfloat16*>(smem + A_OFF_X);  // [2][STRIP][KPAD]

    const int tid  = threadIdx.x;
    const int wid  = tid >> 5;
    const int lane = tid & 31;
    const uint32_t px0 = blockIdx.x * STRIP;

    // ---- build W split [hi | lo] (rows: q0-63 | k64-127 | v128-191) ----
    for (int i = tid; i < 192 * 32; i += 512) {
        int m  = i >> 5;
        int cp = i & 31;
        int c  = cp * 2;
        int mat = m >> 6;
        int ch  = m & 63;
        const float* Wsrc = (mat == 0) ? Wq : (mat == 1) ? Wk : Wv;
        float2 w = *reinterpret_cast<const float2*>(Wsrc + ch * C + c);
        __nv_bfloat16 h0b = __float2bfloat16(w.x);
        __nv_bfloat16 h1b = __float2bfloat16(w.y);
        float l0 = w.x - __bfloat162float(h0b);
        float l1 = w.y - __bfloat162float(h1b);
        uint32_t hi2 = ((uint32_t)*reinterpret_cast<uint16_t*>(&h0b)) |
                       ((uint32_t)*reinterpret_cast<uint16_t*>(&h1b) << 16);
        uint32_t lo2 = pack_bf16x2(l0, l1);
        uint32_t* row = reinterpret_cast<uint32_t*>(Ws + m * KPAD);
        row[cp]      = hi2;
        row[32 + cp] = lo2;
    }
    if (tid < 192) {
        int mat = tid >> 6;
        int ch  = tid & 63;
        bsh[tid] = ((mat == 0) ? bq : (mat == 1) ? bk : bv)[ch];
    }

    // warp tiling: 16 warps = 4 m-groups (48 rows) x 4 n-groups (32 px)
    const int mg  = wid >> 2;
    const int ngA = wid & 3;
    const int lrow = (lane & 7) + ((lane >> 3) & 1) * 8;
    const int lkof = (lane >> 4) * 8;
    const uint32_t xs_base = smem_u32(Xs);
    const uint32_t ws_base = smem_u32(Ws);

    // register-staged X load (8 iters x 2 channels)
    float xr0[8], xr1[8];

    auto loadX = [&](int b) {
        #pragma unroll
        for (int it = 0; it < 8; ++it) {
            int i  = tid + it * 512;
            int cp = i >> 7;                   // STRIP = 128
            int px = i & 127;
            const float* xp = x + (uint32_t)(b * C + cp * 2) * HW + px0 + px;
            xr0[it] = xp[0];
            xr1[it] = xp[HW];
        }
    };
    auto flushX = [&](int bs) {
        __nv_bfloat16* Xd = Xs + bs * XBUF;
        #pragma unroll
        for (int it = 0; it < 8; ++it) {
            int i  = tid + it * 512;
            int cp = i >> 7;
            int px = i & 127;
            float f0 = xr0[it], f1 = xr1[it];
            __nv_bfloat16 h0b = __float2bfloat16(f0);
            __nv_bfloat16 h1b = __float2bfloat16(f1);
            float l0 = f0 - __bfloat162float(h0b);
            float l1 = f1 - __bfloat162float(h1b);
            uint32_t hi2 = ((uint32_t)*reinterpret_cast<uint16_t*>(&h0b)) |
                           ((uint32_t)*reinterpret_cast<uint16_t*>(&h1b) << 16);
            uint32_t lo2 = pack_bf16x2(l0, l1);
            uint32_t* row = reinterpret_cast<uint32_t*>(Xd + px * KPAD);
            row[cp]      = hi2;
            row[32 + cp] = lo2;
        }
    };

    loadX(0);
    flushX(0);
    __syncthreads();      // W + X0 visible

    for (int b = 0; b < Bn; ++b) {
        if (b < 3) loadX(b + 1);     // LDGs drain under the GEMM below

        // ---- GEMM, term-grouped: per t load Ahi/Alo/Bhi/Blo once, 3 terms ----
        const uint32_t xb_base = xs_base + (uint32_t)((b & 1) * XBUF * 2);
        float acc[3][4][4];
        #pragma unroll
        for (int mt = 0; mt < 3; ++mt) {
            float b0v = bsh[mg * 48 + mt * 16 + (lane >> 2)];
            float b1v = bsh[mg * 48 + mt * 16 + (lane >> 2) + 8];
            #pragma unroll
            for (int jn = 0; jn < 4; ++jn) {
                acc[mt][jn][0] = b0v; acc[mt][jn][1] = b0v;
                acc[mt][jn][2] = b1v; acc[mt][jn][3] = b1v;
            }
        }
        #pragma unroll
        for (int t = 0; t < 4; ++t) {
            const int khi = t * 16;            // hi cols 0..63
            const int klo = 64 + t * 16;       // lo cols 64..127
            uint32_t ahi[3][4], alo[3][4];
            #pragma unroll
            for (int mt = 0; mt < 3; ++mt) {
                const uint32_t arow = ws_base +
                    (uint32_t)((mg * 48 + mt * 16 + lrow) * (KPAD * 2));
                ldsm_x4(ahi[mt], arow + (uint32_t)((khi + lkof) * 2));
                ldsm_x4(alo[mt], arow + (uint32_t)((klo + lkof) * 2));
            }
            #pragma unroll
            for (int nt = 0; nt < 2; ++nt) {
                const uint32_t brow = xb_base +
                    (uint32_t)((ngA * 32 + nt * 16 + lrow) * (KPAD * 2));
                uint32_t bhi[4], blo[4];
                ldsm_x4(bhi, brow + (uint32_t)((khi + lkof) * 2));
                ldsm_x4(blo, brow + (uint32_t)((klo + lkof) * 2));
                #pragma unroll
                for (int mt = 0; mt < 3; ++mt) {
                    mma16816(acc[mt][nt * 2 + 0], ahi[mt], bhi[0], bhi[2]);  // Whi*Xhi
                    mma16816(acc[mt][nt * 2 + 1], ahi[mt], bhi[1], bhi[3]);
                    mma16816(acc[mt][nt * 2 + 0], alo[mt], bhi[0], bhi[2]);  // Wlo*Xhi
                    mma16816(acc[mt][nt * 2 + 1], alo[mt], bhi[1], bhi[3]);
                    mma16816(acc[mt][nt * 2 + 0], ahi[mt], blo[0], blo[2]);  // Whi*Xlo
                    mma16816(acc[mt][nt * 2 + 1], ahi[mt], blo[1], blo[3]);
                }
            }
        }

        if (b < 3) flushX((b + 1) & 1);   // LDGs have landed by now

        // ---- store to scratch: [mat][b][ch][px] ----
        #pragma unroll
        for (int mt = 0; mt < 3; ++mt) {
            const int r0 = mg * 48 + mt * 16 + (lane >> 2);
            const int r1 = r0 + 8;
            float* d0 = g_qkv + (uint32_t)(((r0 >> 6) * Bn + b) * C + (r0 & 63)) * HW + px0;
            float* d1 = g_qkv + (uint32_t)(((r1 >> 6) * Bn + b) * C + (r1 & 63)) * HW + px0;
            #pragma unroll
            for (int jn = 0; jn < 4; ++jn) {
                const int col = ngA * 32 + jn * 8 + (lane & 3) * 2;
                *reinterpret_cast<float2*>(d0 + col) = make_float2(acc[mt][jn][0], acc[mt][jn][1]);
                *reinterpret_cast<float2*>(d1 + col) = make_float2(acc[mt][jn][2], acc[mt][jn][3]);
            }
        }
        __syncthreads();
    }
}

// ================= Kernel B: 9-tap per-channel softmax (R13 shape) ==========
constexpr int TB   = 16;            // spatial tile
constexpr int HB   = TB + 2;        // 18 (halo)
constexpr int HPTS = HB * HB;       // 324
constexpr int CSTR = 326;           // channel stride in smem floats
constexpr int B_SMEM = 2 * 16 * CSTR * 4;   // ks + vs = 41728 B (4 CTAs/SM)

__global__ __launch_bounds__(256, 4)
void attn_sm_kernel(float* __restrict__ out)
{
    extern __shared__ char smem[];
    float* ks = reinterpret_cast<float*>(smem);            // [16][CSTR]
    float* vs = ks + 16 * CSTR;                            // [16][CSTR]

    const int b   = blockIdx.z;
    const int ty0 = blockIdx.y * TB;
    const int tx0 = blockIdx.x * TB;
    const int tid = threadIdx.x;

    // compute assignment: pixel pair x 8 channels
    const int pid = tid & 127;
    const int cg8 = tid >> 7;           // 0/1 -> channels 8*cg8..8*cg8+7
    const int spy = pid >> 3;           // 0..15
    const int stx = (pid & 7) * 2;      // 0,2,..,14

    const uint32_t kmat = (uint32_t)(1 * Bn + b) * C * HW;
    const uint32_t vmat = (uint32_t)(2 * Bn + b) * C * HW;
    const uint32_t qmat = (uint32_t)b * C * HW;
    const uint32_t qpix = (uint32_t)(ty0 + spy) * Wd + tx0 + stx;

    const bool interior = (ty0 != 0) && (ty0 != H - TB) && (tx0 != 0) && (tx0 != Wd - TB);
    const uint32_t ibase = (uint32_t)(ty0 - 1) * Wd + (uint32_t)(tx0 - 1);

    #pragma unroll 1
    for (int c0 = 0; c0 < C; c0 += 16) {
        if (c0 > 0) __syncthreads();    // prev compute done before smem overwrite

        // ---- load k,v chunk (uint32 offsets, pure-ALU addressing) ----
        if (interior) {
            for (int i = tid; i < 16 * HPTS; i += 256) {
                int ch = i / HPTS;
                int e  = i - ch * HPTS;
                int hy = e / HB;
                int hx = e - hy * HB;
                uint32_t src = (uint32_t)(c0 + ch) * HW + ibase + (uint32_t)hy * Wd + hx;
                ks[ch * CSTR + e] = g_qkv[kmat + src];
                vs[ch * CSTR + e] = g_qkv[vmat + src];
            }
        } else {
            for (int i = tid; i < 16 * HPTS; i += 256) {
                int ch = i / HPTS;
                int e  = i - ch * HPTS;
                int hy = e / HB;
                int hx = e - hy * HB;
                int gy = ty0 + hy - 1;
                gy = (gy < 0) ? -gy : ((gy >= H) ? (2 * H - 2 - gy) : gy);
                int gx = tx0 + hx - 1;
                gx = (gx < 0) ? -gx : ((gx >= Wd) ? (2 * Wd - 2 - gx) : gx);
                uint32_t src = (uint32_t)(c0 + ch) * HW + (uint32_t)gy * Wd + gx;
                ks[ch * CSTR + e] = g_qkv[kmat + src];
                vs[ch * CSTR + e] = g_qkv[vmat + src];
            }
        }
        __syncthreads();

        // ---- softmax for my 2 pixels x 8 channels ----
        #pragma unroll 1
        for (int r = 0; r < 8; ++r) {
            const int chn = cg8 * 8 + r;            // 0..15
            const uint32_t plane = qmat + (uint32_t)(c0 + chn) * HW;
            const float2 q2 = *reinterpret_cast<const float2*>(g_qkv + plane + qpix);
            const float q0 = q2.x * LOG2E;
            const float q1 = q2.y * LOG2E;
            const float* kr = ks + chn * CSTR;
            const float* vr = vs + chn * CSTR;
            float s0 = 0.f, a0 = 0.f, s1 = 0.f, a1 = 0.f;
            #pragma unroll
            for (int rr = 0; rr < 3; ++rr) {
                const int off = (spy + rr) * HB + stx;
                float2 ka = *reinterpret_cast<const float2*>(kr + off);
                float2 kb = *reinterpret_cast<const float2*>(kr + off + 2);
                float2 va = *reinterpret_cast<const float2*>(vr + off);
                float2 vb = *reinterpret_cast<const float2*>(vr + off + 2);
                float e;
                e = fast_ex2(q0 * ka.x); s0 += e; a0 = fmaf(e, va.x, a0);
                e = fast_ex2(q0 * ka.y); s0 += e; a0 = fmaf(e, va.y, a0);
                e = fast_ex2(q0 * kb.x); s0 += e; a0 = fmaf(e, vb.x, a0);
                e = fast_ex2(q1 * ka.y); s1 += e; a1 = fmaf(e, va.y, a1);
                e = fast_ex2(q1 * kb.x); s1 += e; a1 = fmaf(e, vb.x, a1);
                e = fast_ex2(q1 * kb.y); s1 += e; a1 = fmaf(e, vb.y, a1);
            }
            *reinterpret_cast<float2*>(out + plane + qpix) =
                make_float2(__fdividef(a0, s0), __fdividef(a1, s1));
        }
    }
}

extern "C" void kernel_launch(void* const* d_in, const int* in_sizes, int n_in,
                              void* d_out, int out_size)
{
    const float* x  = (const float*)d_in[0];
    const float* Wq = (const float*)d_in[1];
    const float* bq = (const float*)d_in[2];
    const float* Wk = (const float*)d_in[3];
    const float* bk = (const float*)d_in[4];
    const float* Wv = (const float*)d_in[5];
    const float* bv = (const float*)d_in[6];
    float* out = (float*)d_out;

    cudaFuncSetAttribute(proj_kernel, cudaFuncAttributeMaxDynamicSharedMemorySize, A_SMEM);
    cudaFuncSetAttribute(attn_sm_kernel, cudaFuncAttributeMaxDynamicSharedMemorySize, B_SMEM);

    proj_kernel<<<HW / STRIP, 512, A_SMEM>>>(x, Wq, bq, Wk, bk, Wv, bv);   // 288 CTAs
    dim3 gridB(Wd / TB, H / TB, Bn);                                       // (12,12,4)
    attn_sm_kernel<<<gridB, 256, B_SMEM>>>(out);
}